// round 16
// baseline (speedup 1.0000x reference)
#include <cuda_runtime.h>
#include <cuda_fp16.h>
#include <mma.h>
#include <math.h>

using namespace nvcuda;

// Fixed problem shape: N=100000, E=1600000, IN_F=128, H=4, C=32.
#define MAXN 100000
#define MAXE 1600000
#define F 128
#define HEADS 4
#define NEG_SLOPE 0.2f
#define SCAN_BLK 1024
#define MAX_NB ((MAXN + SCAN_BLK - 1) / SCAN_BLK)

typedef unsigned long long u64;

__device__ __align__(16) __half g_h[MAXN * F];         // projected features (fp16)
__device__ __align__(16) __half g_wh[F * F];           // W in fp16, natural [k][n]
__device__ __align__(16) float g_asrc[MAXN * HEADS];
__device__ __align__(16) float g_adst[MAXN * HEADS];
__device__ int g_cnt[MAXN];
__device__ int g_off[MAXN + 1];
__device__ int g_cur[MAXN];
__device__ int g_bsum[MAX_NB];
__device__ int g_bsumex[MAX_NB];
__device__ int g_csr[MAXE];

// ---------------------------------------------------------------------------
// setup split: W convert (main / proj branch), cnt zero (CSR branch)
// ---------------------------------------------------------------------------
__global__ void wconv_kernel(const float* __restrict__ W) {
    int tid = blockIdx.x * blockDim.x + threadIdx.x;
    if (tid < F * F) g_wh[tid] = __float2half_rn(W[tid]);
}

__global__ void zero_cnt_kernel(int N) {
    int tid = blockIdx.x * blockDim.x + threadIdx.x;
    if (tid < N) g_cnt[tid] = 0;
}

// ---------------------------------------------------------------------------
// proj: 64 rows x 128 cols per 256-thread block (R9/R11 config).
// ---------------------------------------------------------------------------
#define BST 136
#define STF 136
#define PROJ_ROWS_BLK 64

__global__ __launch_bounds__(256, 1) void proj_kernel(const float* __restrict__ x, int N) {
    __shared__ __align__(16) __half bs[F * BST];
    __shared__ __align__(16) __half as_[16 * BST];
    __shared__ __align__(16) float  st[16 * STF];

    int t = threadIdx.x;
    int w = t >> 5;

    const int4* wsrc = reinterpret_cast<const int4*>(g_wh);
    #pragma unroll
    for (int i = 0; i < 8; i++) {
        int idx = t + i * 256;
        int k   = idx >> 4;
        int c8  = (idx & 15) * 8;
        *reinterpret_cast<int4*>(&bs[k * BST + c8]) = wsrc[idx];
    }
    __syncthreads();

    wmma::fragment<wmma::matrix_b, 16, 16, 16, __half, wmma::row_major> bfrag[8];
    #pragma unroll
    for (int kt = 0; kt < 8; kt++)
        wmma::load_matrix_sync(bfrag[kt], &bs[kt * 16 * BST + w * 16], BST);

    int row0 = blockIdx.x * PROJ_ROWS_BLK;

    for (int rt = 0; rt < 4; rt++) {
        int rbase = row0 + rt * 16;

        #pragma unroll
        for (int i = 0; i < 2; i++) {
            int idx = t + i * 256;
            int r = idx >> 5;
            int c = (idx & 31) * 4;
            int gr = rbase + r;
            float4 v = (gr < N) ? *reinterpret_cast<const float4*>(&x[(size_t)gr * F + c])
                                : make_float4(0.f, 0.f, 0.f, 0.f);
            __half2 h0 = __floats2half2_rn(v.x, v.y);
            __half2 h1 = __floats2half2_rn(v.z, v.w);
            *reinterpret_cast<__half2*>(&as_[r * BST + c])     = h0;
            *reinterpret_cast<__half2*>(&as_[r * BST + c + 2]) = h1;
        }
        __syncthreads();

        wmma::fragment<wmma::matrix_a, 16, 16, 16, __half, wmma::row_major> afrag;
        wmma::fragment<wmma::accumulator, 16, 16, 16, float> cfrag;
        wmma::fill_fragment(cfrag, 0.0f);
        #pragma unroll
        for (int kt = 0; kt < 8; kt++) {
            wmma::load_matrix_sync(afrag, &as_[kt * 16], BST);
            wmma::mma_sync(cfrag, afrag, bfrag[kt], cfrag);
        }
        wmma::store_matrix_sync(&st[w * 16], cfrag, STF, wmma::mem_row_major);
        __syncthreads();

        #pragma unroll
        for (int i = 0; i < 2; i++) {
            int idx = t + i * 256;
            int r = idx >> 5;
            int c = (idx & 31) * 4;
            int gr = rbase + r;
            if (gr < N) {
                const float* sp = &st[r * STF + c];
                __half2 h0 = __floats2half2_rn(sp[0], sp[1]);
                __half2 h1 = __floats2half2_rn(sp[2], sp[3]);
                __half2 pair[2] = {h0, h1};
                *reinterpret_cast<u64*>(&g_h[(size_t)gr * F + c]) =
                    *reinterpret_cast<u64*>(pair);
            }
        }
        __syncthreads();
    }
}

// ---------------------------------------------------------------------------
// asrc: a_src/a_dst from fp16 h (coalesced u64 loads).
// ---------------------------------------------------------------------------
#define AR 4
__global__ void asrc_kernel(const float* __restrict__ att_src,
                            const float* __restrict__ att_dst, int N) {
    int gw   = (blockIdx.x * blockDim.x + threadIdx.x) >> 5;
    int lane = threadIdx.x & 31;
    int row0 = gw * AR;
    if (row0 >= N) return;

    int head  = lane >> 3;
    int cbase = (lane & 7) * 4;
    float4 as = *reinterpret_cast<const float4*>(&att_src[head * 32 + cbase]);
    float4 ad = *reinterpret_cast<const float4*>(&att_dst[head * 32 + cbase]);

    u64 u[AR];
    #pragma unroll
    for (int i = 0; i < AR; i++) {
        int r = row0 + i;
        u[i] = (r < N) ? *reinterpret_cast<const u64*>(&g_h[(size_t)r * F + lane * 4]) : 0ULL;
    }

    #pragma unroll
    for (int i = 0; i < AR; i++) {
        int r = row0 + i;
        if (r >= N) break;
        float2 f01 = __half22float2(reinterpret_cast<__half2*>(&u[i])[0]);
        float2 f23 = __half22float2(reinterpret_cast<__half2*>(&u[i])[1]);
        float s = f01.x * as.x + f01.y * as.y + f23.x * as.z + f23.y * as.w;
        float d = f01.x * ad.x + f01.y * ad.y + f23.x * ad.z + f23.y * ad.w;
        #pragma unroll
        for (int o = 4; o > 0; o >>= 1) {
            s += __shfl_xor_sync(0xFFFFFFFFu, s, o);
            d += __shfl_xor_sync(0xFFFFFFFFu, d, o);
        }
        if ((lane & 7) == 0) {
            g_asrc[r * HEADS + head] = s;
            g_adst[r * HEADS + head] = d;
        }
    }
}

// ---------------------------------------------------------------------------
// CSR build
// ---------------------------------------------------------------------------
__global__ void hist_kernel(const int* __restrict__ ei, int E) {
    int e0 = (blockIdx.x * blockDim.x + threadIdx.x) * 4;
    if (e0 + 3 < E) {
        int4 d = *reinterpret_cast<const int4*>(&ei[E + e0]);
        atomicAdd(&g_cnt[d.x], 1);
        atomicAdd(&g_cnt[d.y], 1);
        atomicAdd(&g_cnt[d.z], 1);
        atomicAdd(&g_cnt[d.w], 1);
    } else {
        for (int e = e0; e < E; e++) atomicAdd(&g_cnt[ei[E + e]], 1);
    }
}

__global__ void scan1_kernel(int N) {
    __shared__ int ws[32];
    int t = threadIdx.x;
    int g = blockIdx.x * SCAN_BLK + t;
    int lane = t & 31, wid = t >> 5;
    int v = (g < N) ? g_cnt[g] : 0;

    int xv = v;
    #pragma unroll
    for (int o = 1; o < 32; o <<= 1) {
        int y = __shfl_up_sync(0xFFFFFFFFu, xv, o);
        if (lane >= o) xv += y;
    }
    if (lane == 31) ws[wid] = xv;
    __syncthreads();
    if (wid == 0) {
        int y = ws[lane];
        #pragma unroll
        for (int o = 1; o < 32; o <<= 1) {
            int z = __shfl_up_sync(0xFFFFFFFFu, y, o);
            if (lane >= o) y += z;
        }
        ws[lane] = y;
    }
    __syncthreads();
    int incl = xv + (wid > 0 ? ws[wid - 1] : 0);
    if (g < N) g_off[g] = incl - v;
    if (t == SCAN_BLK - 1) g_bsum[blockIdx.x] = incl;
}

__global__ void scan2_kernel(int NB) {
    __shared__ int ws[4];
    int t = threadIdx.x;
    int lane = t & 31, wid = t >> 5;
    int v = (t < NB) ? g_bsum[t] : 0;
    int xv = v;
    #pragma unroll
    for (int o = 1; o < 32; o <<= 1) {
        int y = __shfl_up_sync(0xFFFFFFFFu, xv, o);
        if (lane >= o) xv += y;
    }
    if (lane == 31) ws[wid] = xv;
    __syncthreads();
    int add = 0;
    for (int i = 0; i < wid; i++) add += ws[i];
    if (t < NB) g_bsumex[t] = xv + add - v;
}

__global__ void scan3_kernel(int N, int E) {
    int g = blockIdx.x * blockDim.x + threadIdx.x;
    if (g < N) {
        int v = g_off[g] + g_bsumex[g / SCAN_BLK];
        g_off[g] = v;
        g_cur[g] = v;
    }
    if (g == 0) g_off[N] = E;
}

__global__ void fill_kernel(const int* __restrict__ ei, int E) {
    int e0 = (blockIdx.x * blockDim.x + threadIdx.x) * 4;
    if (e0 + 3 < E) {
        int4 s = *reinterpret_cast<const int4*>(&ei[e0]);
        int4 d = *reinterpret_cast<const int4*>(&ei[E + e0]);
        g_csr[atomicAdd(&g_cur[d.x], 1)] = s.x;
        g_csr[atomicAdd(&g_cur[d.y], 1)] = s.y;
        g_csr[atomicAdd(&g_cur[d.z], 1)] = s.z;
        g_csr[atomicAdd(&g_cur[d.w], 1)] = s.w;
    } else {
        for (int e = e0; e < E; e++) {
            g_csr[atomicAdd(&g_cur[ei[E + e]], 1)] = ei[e];
        }
    }
}

// ---------------------------------------------------------------------------
// Gather: warp per dst node (exact R12 loop — best measured variant).
// ---------------------------------------------------------------------------
__device__ __forceinline__ float lrelu(float v) {
    return v > 0.0f ? v : NEG_SLOPE * v;
}
__device__ __forceinline__ void acc_h16(float4& acc, float p, const __half* hp) {
    u64 u = *reinterpret_cast<const u64*>(hp);
    __half2 h01 = reinterpret_cast<__half2*>(&u)[0];
    __half2 h23 = reinterpret_cast<__half2*>(&u)[1];
    float2 f01 = __half22float2(h01);
    float2 f23 = __half22float2(h23);
    acc.x = fmaf(p, f01.x, acc.x);
    acc.y = fmaf(p, f01.y, acc.y);
    acc.z = fmaf(p, f23.x, acc.z);
    acc.w = fmaf(p, f23.y, acc.w);
}

#define GW 8
__global__ void gather_kernel(float* __restrict__ out,
                              const float* __restrict__ bias, int N) {
    __shared__ int    ssrc[GW][32];
    __shared__ float4 sp[GW][32];
    int wip  = threadIdx.x >> 5;
    int i    = blockIdx.x * GW + wip;
    int lane = threadIdx.x & 31;
    if (i >= N) return;

    int head = lane >> 3;
    float4 adv = *reinterpret_cast<const float4*>(&g_adst[i * HEADS]);
    float ad_h = (head == 0) ? adv.x : (head == 1) ? adv.y : (head == 2) ? adv.z : adv.w;

    float p0 = __expf(lrelu(g_asrc[i * HEADS + head] + ad_h));
    float4 acc = make_float4(0.f, 0.f, 0.f, 0.f);
    acc_h16(acc, p0, &g_h[(size_t)i * F + lane * 4]);
    float den = p0;

    int beg = g_off[i];
    int end = g_off[i + 1];

    for (int base = beg; base < end; base += 32) {
        int k = base + lane;
        int sj = (k < end) ? g_csr[k] : 0;
        ssrc[wip][lane] = sj;
        float4 a = *reinterpret_cast<const float4*>(&g_asrc[sj * HEADS]);
        float4 p4;
        p4.x = __expf(lrelu(a.x + adv.x));
        p4.y = __expf(lrelu(a.y + adv.y));
        p4.z = __expf(lrelu(a.z + adv.z));
        p4.w = __expf(lrelu(a.w + adv.w));
        sp[wip][lane] = p4;
        __syncwarp();

        int cnt = end - base;
        if (cnt >= 32) {
            #pragma unroll 8
            for (int j = 0; j < 32; j++) {
                int s = ssrc[wip][j];
                float p = reinterpret_cast<const float*>(&sp[wip][j])[head];
                acc_h16(acc, p, &g_h[(size_t)s * F + lane * 4]);
                den += p;
            }
        } else {
            for (int j = 0; j < cnt; j++) {
                int s = ssrc[wip][j];
                float p = reinterpret_cast<const float*>(&sp[wip][j])[head];
                acc_h16(acc, p, &g_h[(size_t)s * F + lane * 4]);
                den += p;
            }
        }
        __syncwarp();
    }

    float inv = 1.0f / (den + 1e-16f);
    float4 b = *reinterpret_cast<const float4*>(&bias[lane * 4]);
    float4 r;
    r.x = fmaf(acc.x, inv, b.x);
    r.y = fmaf(acc.y, inv, b.y);
    r.z = fmaf(acc.z, inv, b.z);
    r.w = fmaf(acc.w, inv, b.w);
    *reinterpret_cast<float4*>(&out[i * F + lane * 4]) = r;
}

// ---------------------------------------------------------------------------
// Launch: fork at the very start — CSR branch (incl. its own cnt-zero) on sB;
// W-convert + proj + asrc on main; join at gather.
// ---------------------------------------------------------------------------
extern "C" void kernel_launch(void* const* d_in, const int* in_sizes, int n_in,
                              void* d_out, int out_size) {
    const float* x       = (const float*)d_in[0];
    const int*   ei      = (const int*)d_in[1];
    const float* W       = (const float*)d_in[2];
    const float* att_src = (const float*)d_in[3];
    const float* att_dst = (const float*)d_in[4];
    const float* bias    = (const float*)d_in[5];
    float*       out     = (float*)d_out;

    int N = in_sizes[0] / F;
    int E = in_sizes[1] / 2;
    int NB = (N + SCAN_BLK - 1) / SCAN_BLK;

    static cudaStream_t sB = nullptr;
    static cudaEvent_t evFork = nullptr, evJoin = nullptr;
    if (sB == nullptr) {
        cudaStreamCreateWithFlags(&sB, cudaStreamNonBlocking);
        cudaEventCreateWithFlags(&evFork, cudaEventDisableTiming);
        cudaEventCreateWithFlags(&evJoin, cudaEventDisableTiming);
    }

    // fork immediately: both branches start from the same (empty) point
    cudaEventRecord(evFork, 0);
    cudaStreamWaitEvent(sB, evFork, 0);

    // branch B (sB): CSR build (owns its cnt-zero)
    zero_cnt_kernel<<<(N + 255) / 256, 256, 0, sB>>>(N);
    hist_kernel<<<(E / 4 + 255) / 256, 256, 0, sB>>>(ei, E);
    scan1_kernel<<<NB, SCAN_BLK, 0, sB>>>(N);
    scan2_kernel<<<1, 128, 0, sB>>>(NB);
    scan3_kernel<<<(N + 255) / 256, 256, 0, sB>>>(N, E);
    fill_kernel<<<(E / 4 + 255) / 256, 256, 0, sB>>>(ei, E);
    cudaEventRecord(evJoin, sB);

    // main: W convert -> proj -> asrc
    wconv_kernel<<<(F * F + 255) / 256, 256>>>(W);
    proj_kernel<<<(N + PROJ_ROWS_BLK - 1) / PROJ_ROWS_BLK, 256>>>(x, N);
    int awarps = (N + AR - 1) / AR;
    asrc_kernel<<<(awarps * 32 + 255) / 256, 256>>>(att_src, att_dst, N);

    cudaStreamWaitEvent(0, evJoin, 0);
    gather_kernel<<<(N + GW - 1) / GW, GW * 32>>>(out, bias, N);
}

// round 17
// speedup vs baseline: 1.0918x; 1.0918x over previous
#include <cuda_runtime.h>
#include <cuda_fp16.h>
#include <mma.h>
#include <math.h>

using namespace nvcuda;

// Fixed problem shape: N=100000, E=1600000, IN_F=128, H=4, C=32.
#define MAXN 100000
#define MAXE 1600000
#define F 128
#define HEADS 4
#define NEG_SLOPE 0.2f
#define SCAN_BLK 1024
#define MAX_NB ((MAXN + SCAN_BLK - 1) / SCAN_BLK)

typedef unsigned long long u64;

__device__ __align__(16) __half g_h[MAXN * F];         // projected features (fp16)
__device__ __align__(16) __half g_wh[F * F];           // W in fp16, natural [k][n]
__device__ __align__(16) float g_asrc[MAXN * HEADS];   // src attention half only
__device__ int g_cnt[MAXN];
__device__ int g_off[MAXN + 1];
__device__ int g_cur[MAXN];
__device__ int g_bsum[MAX_NB];
__device__ int g_bsumex[MAX_NB];
__device__ int g_csr[MAXE];

// ---------------------------------------------------------------------------
// setup: zero histogram + convert W to fp16 (combined, R12 style)
// ---------------------------------------------------------------------------
__global__ void setup_kernel(const float* __restrict__ W, int N) {
    int tid = blockIdx.x * blockDim.x + threadIdx.x;
    if (tid < N) g_cnt[tid] = 0;
    if (tid < F * F) g_wh[tid] = __float2half_rn(W[tid]);
}

// ---------------------------------------------------------------------------
// proj: 64 rows x 128 cols per 256-thread block (R9/R11/R12 config).
// ---------------------------------------------------------------------------
#define BST 136
#define STF 136
#define PROJ_ROWS_BLK 64

__global__ __launch_bounds__(256, 1) void proj_kernel(const float* __restrict__ x, int N) {
    __shared__ __align__(16) __half bs[F * BST];
    __shared__ __align__(16) __half as_[16 * BST];
    __shared__ __align__(16) float  st[16 * STF];

    int t = threadIdx.x;
    int w = t >> 5;

    const int4* wsrc = reinterpret_cast<const int4*>(g_wh);
    #pragma unroll
    for (int i = 0; i < 8; i++) {
        int idx = t + i * 256;
        int k   = idx >> 4;
        int c8  = (idx & 15) * 8;
        *reinterpret_cast<int4*>(&bs[k * BST + c8]) = wsrc[idx];
    }
    __syncthreads();

    wmma::fragment<wmma::matrix_b, 16, 16, 16, __half, wmma::row_major> bfrag[8];
    #pragma unroll
    for (int kt = 0; kt < 8; kt++)
        wmma::load_matrix_sync(bfrag[kt], &bs[kt * 16 * BST + w * 16], BST);

    int row0 = blockIdx.x * PROJ_ROWS_BLK;

    for (int rt = 0; rt < 4; rt++) {
        int rbase = row0 + rt * 16;

        #pragma unroll
        for (int i = 0; i < 2; i++) {
            int idx = t + i * 256;
            int r = idx >> 5;
            int c = (idx & 31) * 4;
            int gr = rbase + r;
            float4 v = (gr < N) ? *reinterpret_cast<const float4*>(&x[(size_t)gr * F + c])
                                : make_float4(0.f, 0.f, 0.f, 0.f);
            __half2 h0 = __floats2half2_rn(v.x, v.y);
            __half2 h1 = __floats2half2_rn(v.z, v.w);
            *reinterpret_cast<__half2*>(&as_[r * BST + c])     = h0;
            *reinterpret_cast<__half2*>(&as_[r * BST + c + 2]) = h1;
        }
        __syncthreads();

        wmma::fragment<wmma::matrix_a, 16, 16, 16, __half, wmma::row_major> afrag;
        wmma::fragment<wmma::accumulator, 16, 16, 16, float> cfrag;
        wmma::fill_fragment(cfrag, 0.0f);
        #pragma unroll
        for (int kt = 0; kt < 8; kt++) {
            wmma::load_matrix_sync(afrag, &as_[kt * 16], BST);
            wmma::mma_sync(cfrag, afrag, bfrag[kt], cfrag);
        }
        wmma::store_matrix_sync(&st[w * 16], cfrag, STF, wmma::mem_row_major);
        __syncthreads();

        #pragma unroll
        for (int i = 0; i < 2; i++) {
            int idx = t + i * 256;
            int r = idx >> 5;
            int c = (idx & 31) * 4;
            int gr = rbase + r;
            if (gr < N) {
                const float* sp = &st[r * STF + c];
                __half2 h0 = __floats2half2_rn(sp[0], sp[1]);
                __half2 h1 = __floats2half2_rn(sp[2], sp[3]);
                __half2 pair[2] = {h0, h1};
                *reinterpret_cast<u64*>(&g_h[(size_t)gr * F + c]) =
                    *reinterpret_cast<u64*>(pair);
            }
        }
        __syncthreads();
    }
}

// ---------------------------------------------------------------------------
// asrc: a_src ONLY from fp16 h (a_dst is computed in-place by gather).
// ---------------------------------------------------------------------------
#define AR 4
__global__ void asrc_kernel(const float* __restrict__ att_src, int N) {
    int gw   = (blockIdx.x * blockDim.x + threadIdx.x) >> 5;
    int lane = threadIdx.x & 31;
    int row0 = gw * AR;
    if (row0 >= N) return;

    int head  = lane >> 3;
    int cbase = (lane & 7) * 4;
    float4 as = *reinterpret_cast<const float4*>(&att_src[head * 32 + cbase]);

    u64 u[AR];
    #pragma unroll
    for (int i = 0; i < AR; i++) {
        int r = row0 + i;
        u[i] = (r < N) ? *reinterpret_cast<const u64*>(&g_h[(size_t)r * F + lane * 4]) : 0ULL;
    }

    #pragma unroll
    for (int i = 0; i < AR; i++) {
        int r = row0 + i;
        if (r >= N) break;
        float2 f01 = __half22float2(reinterpret_cast<__half2*>(&u[i])[0]);
        float2 f23 = __half22float2(reinterpret_cast<__half2*>(&u[i])[1]);
        float s = f01.x * as.x + f01.y * as.y + f23.x * as.z + f23.y * as.w;
        #pragma unroll
        for (int o = 4; o > 0; o >>= 1) {
            s += __shfl_xor_sync(0xFFFFFFFFu, s, o);
        }
        if ((lane & 7) == 0) {
            g_asrc[r * HEADS + head] = s;
        }
    }
}

// ---------------------------------------------------------------------------
// CSR build (R12 kernels; parallel scan2)
// ---------------------------------------------------------------------------
__global__ void hist_kernel(const int* __restrict__ ei, int E) {
    int e0 = (blockIdx.x * blockDim.x + threadIdx.x) * 4;
    if (e0 + 3 < E) {
        int4 d = *reinterpret_cast<const int4*>(&ei[E + e0]);
        atomicAdd(&g_cnt[d.x], 1);
        atomicAdd(&g_cnt[d.y], 1);
        atomicAdd(&g_cnt[d.z], 1);
        atomicAdd(&g_cnt[d.w], 1);
    } else {
        for (int e = e0; e < E; e++) atomicAdd(&g_cnt[ei[E + e]], 1);
    }
}

__global__ void scan1_kernel(int N) {
    __shared__ int ws[32];
    int t = threadIdx.x;
    int g = blockIdx.x * SCAN_BLK + t;
    int lane = t & 31, wid = t >> 5;
    int v = (g < N) ? g_cnt[g] : 0;

    int xv = v;
    #pragma unroll
    for (int o = 1; o < 32; o <<= 1) {
        int y = __shfl_up_sync(0xFFFFFFFFu, xv, o);
        if (lane >= o) xv += y;
    }
    if (lane == 31) ws[wid] = xv;
    __syncthreads();
    if (wid == 0) {
        int y = ws[lane];
        #pragma unroll
        for (int o = 1; o < 32; o <<= 1) {
            int z = __shfl_up_sync(0xFFFFFFFFu, y, o);
            if (lane >= o) y += z;
        }
        ws[lane] = y;
    }
    __syncthreads();
    int incl = xv + (wid > 0 ? ws[wid - 1] : 0);
    if (g < N) g_off[g] = incl - v;
    if (t == SCAN_BLK - 1) g_bsum[blockIdx.x] = incl;
}

__global__ void scan2_kernel(int NB) {
    __shared__ int ws[4];
    int t = threadIdx.x;
    int lane = t & 31, wid = t >> 5;
    int v = (t < NB) ? g_bsum[t] : 0;
    int xv = v;
    #pragma unroll
    for (int o = 1; o < 32; o <<= 1) {
        int y = __shfl_up_sync(0xFFFFFFFFu, xv, o);
        if (lane >= o) xv += y;
    }
    if (lane == 31) ws[wid] = xv;
    __syncthreads();
    int add = 0;
    for (int i = 0; i < wid; i++) add += ws[i];
    if (t < NB) g_bsumex[t] = xv + add - v;
}

__global__ void scan3_kernel(int N, int E) {
    int g = blockIdx.x * blockDim.x + threadIdx.x;
    if (g < N) {
        int v = g_off[g] + g_bsumex[g / SCAN_BLK];
        g_off[g] = v;
        g_cur[g] = v;
    }
    if (g == 0) g_off[N] = E;
}

__global__ void fill_kernel(const int* __restrict__ ei, int E) {
    int e0 = (blockIdx.x * blockDim.x + threadIdx.x) * 4;
    if (e0 + 3 < E) {
        int4 s = *reinterpret_cast<const int4*>(&ei[e0]);
        int4 d = *reinterpret_cast<const int4*>(&ei[E + e0]);
        g_csr[atomicAdd(&g_cur[d.x], 1)] = s.x;
        g_csr[atomicAdd(&g_cur[d.y], 1)] = s.y;
        g_csr[atomicAdd(&g_cur[d.z], 1)] = s.z;
        g_csr[atomicAdd(&g_cur[d.w], 1)] = s.w;
    } else {
        for (int e = e0; e < E; e++) {
            g_csr[atomicAdd(&g_cur[ei[E + e]], 1)] = ei[e];
        }
    }
}

// ---------------------------------------------------------------------------
// Gather: warp per dst node (R12 loop). a_dst computed in-place from the
// self h-row: per-head 8-lane segmented dot with att_dst, then broadcast.
// ---------------------------------------------------------------------------
__device__ __forceinline__ float lrelu(float v) {
    return v > 0.0f ? v : NEG_SLOPE * v;
}
__device__ __forceinline__ void acc_h16(float4& acc, float p, const __half* hp) {
    u64 u = *reinterpret_cast<const u64*>(hp);
    __half2 h01 = reinterpret_cast<__half2*>(&u)[0];
    __half2 h23 = reinterpret_cast<__half2*>(&u)[1];
    float2 f01 = __half22float2(h01);
    float2 f23 = __half22float2(h23);
    acc.x = fmaf(p, f01.x, acc.x);
    acc.y = fmaf(p, f01.y, acc.y);
    acc.z = fmaf(p, f23.x, acc.z);
    acc.w = fmaf(p, f23.y, acc.w);
}

#define GW 8
__global__ void gather_kernel(float* __restrict__ out,
                              const float* __restrict__ bias,
                              const float* __restrict__ att_dst, int N) {
    __shared__ int    ssrc[GW][32];
    __shared__ float4 sp[GW][32];
    int wip  = threadIdx.x >> 5;
    int i    = blockIdx.x * GW + wip;
    int lane = threadIdx.x & 31;
    if (i >= N) return;

    int head = lane >> 3;

    // self h row (reused for a_dst and the self-loop accumulation)
    u64 selfh = *reinterpret_cast<const u64*>(&g_h[(size_t)i * F + lane * 4]);
    float2 sf01 = __half22float2(reinterpret_cast<__half2*>(&selfh)[0]);
    float2 sf23 = __half22float2(reinterpret_cast<__half2*>(&selfh)[1]);

    // a_dst[i][head]: lane covers att_dst cols [lane*4, lane*4+4) exactly
    float4 attd = *reinterpret_cast<const float4*>(&att_dst[lane * 4]);
    float dloc = sf01.x * attd.x + sf01.y * attd.y + sf23.x * attd.z + sf23.y * attd.w;
    #pragma unroll
    for (int o = 4; o > 0; o >>= 1)
        dloc += __shfl_xor_sync(0xFFFFFFFFu, dloc, o);
    float ad_h = dloc;                       // own head's value (group-uniform)
    float4 adv;
    adv.x = __shfl_sync(0xFFFFFFFFu, dloc, 0);
    adv.y = __shfl_sync(0xFFFFFFFFu, dloc, 8);
    adv.z = __shfl_sync(0xFFFFFFFFu, dloc, 16);
    adv.w = __shfl_sync(0xFFFFFFFFu, dloc, 24);

    float p0 = __expf(lrelu(g_asrc[i * HEADS + head] + ad_h));
    float4 acc;
    acc.x = p0 * sf01.x;
    acc.y = p0 * sf01.y;
    acc.z = p0 * sf23.x;
    acc.w = p0 * sf23.y;
    float den = p0;

    int beg = g_off[i];
    int end = g_off[i + 1];

    for (int base = beg; base < end; base += 32) {
        int k = base + lane;
        int sj = (k < end) ? g_csr[k] : 0;
        ssrc[wip][lane] = sj;
        float4 a = *reinterpret_cast<const float4*>(&g_asrc[sj * HEADS]);
        float4 p4;
        p4.x = __expf(lrelu(a.x + adv.x));
        p4.y = __expf(lrelu(a.y + adv.y));
        p4.z = __expf(lrelu(a.z + adv.z));
        p4.w = __expf(lrelu(a.w + adv.w));
        sp[wip][lane] = p4;
        __syncwarp();

        int cnt = end - base;
        if (cnt >= 32) {
            #pragma unroll 8
            for (int j = 0; j < 32; j++) {
                int s = ssrc[wip][j];
                float p = reinterpret_cast<const float*>(&sp[wip][j])[head];
                acc_h16(acc, p, &g_h[(size_t)s * F + lane * 4]);
                den += p;
            }
        } else {
            for (int j = 0; j < cnt; j++) {
                int s = ssrc[wip][j];
                float p = reinterpret_cast<const float*>(&sp[wip][j])[head];
                acc_h16(acc, p, &g_h[(size_t)s * F + lane * 4]);
                den += p;
            }
        }
        __syncwarp();
    }

    float inv = 1.0f / (den + 1e-16f);
    float4 b = *reinterpret_cast<const float4*>(&bias[lane * 4]);
    float4 r;
    r.x = fmaf(acc.x, inv, b.x);
    r.y = fmaf(acc.y, inv, b.y);
    r.z = fmaf(acc.z, inv, b.z);
    r.w = fmaf(acc.w, inv, b.w);
    *reinterpret_cast<float4*>(&out[i * F + lane * 4]) = r;
}

// ---------------------------------------------------------------------------
// Launch: exact R12 topology (setup on main -> fork -> CSR on sB;
// proj + asrc on main; join at gather).
// ---------------------------------------------------------------------------
extern "C" void kernel_launch(void* const* d_in, const int* in_sizes, int n_in,
                              void* d_out, int out_size) {
    const float* x       = (const float*)d_in[0];
    const int*   ei      = (const int*)d_in[1];
    const float* W       = (const float*)d_in[2];
    const float* att_src = (const float*)d_in[3];
    const float* att_dst = (const float*)d_in[4];
    const float* bias    = (const float*)d_in[5];
    float*       out     = (float*)d_out;

    int N = in_sizes[0] / F;
    int E = in_sizes[1] / 2;
    int NB = (N + SCAN_BLK - 1) / SCAN_BLK;

    static cudaStream_t sB = nullptr;
    static cudaEvent_t evFork = nullptr, evJoin = nullptr;
    if (sB == nullptr) {
        cudaStreamCreateWithFlags(&sB, cudaStreamNonBlocking);
        cudaEventCreateWithFlags(&evFork, cudaEventDisableTiming);
        cudaEventCreateWithFlags(&evJoin, cudaEventDisableTiming);
    }

    setup_kernel<<<(N + 255) / 256, 256>>>(W, N);

    cudaEventRecord(evFork, 0);
    cudaStreamWaitEvent(sB, evFork, 0);
    hist_kernel<<<(E / 4 + 255) / 256, 256, 0, sB>>>(ei, E);
    scan1_kernel<<<NB, SCAN_BLK, 0, sB>>>(N);
    scan2_kernel<<<1, 128, 0, sB>>>(NB);
    scan3_kernel<<<(N + 255) / 256, 256, 0, sB>>>(N, E);
    fill_kernel<<<(E / 4 + 255) / 256, 256, 0, sB>>>(ei, E);
    cudaEventRecord(evJoin, sB);

    proj_kernel<<<(N + PROJ_ROWS_BLK - 1) / PROJ_ROWS_BLK, 256>>>(x, N);
    int awarps = (N + AR - 1) / AR;
    asrc_kernel<<<(awarps * 32 + 255) / 256, 256>>>(att_src, N);

    cudaStreamWaitEvent(0, evJoin, 0);
    gather_kernel<<<(N + GW - 1) / GW, GW * 32>>>(out, bias, att_dst, N);
}